// round 5
// baseline (speedup 1.0000x reference)
#include <cuda_runtime.h>

typedef unsigned long long u64;

__device__ __forceinline__ u64 bc2(float v) {
    u64 r; asm("mov.b64 %0, {%1, %1};" : "=l"(r) : "f"(v)); return r;
}
__device__ __forceinline__ void fma2(u64& c, u64 a, u64 b) {
    asm("fma.rn.f32x2 %0, %1, %2, %0;" : "+l"(c) : "l"(a), "l"(b));
}
__device__ __forceinline__ float2 up2(u64 v) {
    float lo, hi; asm("mov.b64 {%0, %1}, %2;" : "=f"(lo), "=f"(hi) : "l"(v));
    return make_float2(lo, hi);
}

// -------- scratch (no allocation allowed) --------
__device__ float g_xt[64*256*512];
__device__ float g_h1[64*256*512];
__device__ float g_h2[64*256*256];
__device__ float g_h3[64*512*256];
__device__ float g_h4[64*512*128];
__device__ float g_z [64*512*128];
__device__ float g_zq[64*512*128];
__device__ float g_zqr[64*512*128];
__device__ float g_g1[64*512*128];
__device__ float g_g2[64*512*256];
__device__ float g_g3[64*256*256];
__device__ float g_g4[64*256*512];
__device__ float g_cbn[512];
__device__ float g_zn[64*128];
__device__ float g_bs[64*4*128];
__device__ int   g_bi[64*4*128];
__device__ int   g_idx[64*128];
__device__ double g_part[256];

// -------- [B,T,F] -> [B,F,T] --------
__global__ void transpose_in_k(const float* __restrict__ x, float* __restrict__ xt)
{
    __shared__ float tile[32][33];
    int b = blockIdx.z, t0 = blockIdx.x*32, f0 = blockIdx.y*32;
    int tx = threadIdx.x, ty = threadIdx.y;
#pragma unroll
    for (int r = 0; r < 32; r += 8)
        tile[ty+r][tx] = x[((size_t)b*512 + (t0+ty+r))*256 + f0+tx];
    __syncthreads();
#pragma unroll
    for (int r = 0; r < 32; r += 8)
        xt[((size_t)b*256 + (f0+ty+r))*512 + t0+tx] = tile[tx][ty+r];
}

// -------- conv1d implicit GEMM, pad=1, 512 threads, tile 128co x TTt --------
// per-thread: 4 cout (2 u64 pairs) x TPT t. TPT=8 (stride1,K=3) / 4 (stride2,K=4).
template <int CIN, int COUT, int K, int STRIDE, int TT, bool RELU, bool TROUT>
__global__ __launch_bounds__(512, 2)
void conv1d_k(const float* __restrict__ x, const float* __restrict__ w,
              const float* __restrict__ bias, float* __restrict__ y,
              int Tin, int Tout)
{
    static_assert((STRIDE==1 && K==3) || (STRIDE==2 && K==4), "layer shapes");
    constexpr int TPT   = (STRIDE == 1) ? 8 : 4;
    constexpr int XSPAN = (TT-1)*STRIDE + K;
    constexpr int XPAD  = (XSPAN + 3) & ~3;
    constexpr int XR    = (TPT-1)*STRIDE + K;       // = 10 in both cases
    __shared__ float Ws[K][8][128];
    __shared__ float Xs[8][XPAD];

    int b = blockIdx.z, co0 = blockIdx.y*128, t0 = blockIdx.x*TT;
    int tid = threadIdx.x, t_th = tid & 15, co_th = tid >> 4;   // 16 x 32
    int tin0 = t0*STRIDE - 1;

    u64 acc[2][TPT];
#pragma unroll
    for (int u = 0; u < 2; u++)
#pragma unroll
        for (int j = 0; j < TPT; j++) acc[u][j] = 0ULL;

    for (int ci0 = 0; ci0 < CIN; ci0 += 8) {
        for (int i = tid; i < K*8*128; i += 512) {
            int co = i & 127, r = i >> 7, ci = r & 7, k = r >> 3;
            Ws[k][ci][co] = w[((size_t)(co0+co)*CIN + ci0+ci)*K + k];
        }
        for (int i = tid; i < 8*XPAD; i += 512) {
            int ci = i / XPAD, tt = i - ci*XPAD, gt = tin0 + tt;
            float v = 0.f;
            if (tt < XSPAN && gt >= 0 && gt < Tin)
                v = x[((size_t)b*CIN + ci0+ci)*Tin + gt];
            Xs[ci][tt] = v;
        }
        __syncthreads();
#pragma unroll
        for (int ci = 0; ci < 8; ci++) {
            float xr[XR];
            const float* xp = &Xs[ci][t_th*TPT*STRIDE];
            {
                float4 v0 = *reinterpret_cast<const float4*>(xp);
                float4 v1 = *reinterpret_cast<const float4*>(xp + 4);
                xr[0]=v0.x; xr[1]=v0.y; xr[2]=v0.z; xr[3]=v0.w;
                xr[4]=v1.x; xr[5]=v1.y; xr[6]=v1.z; xr[7]=v1.w;
                xr[8]=xp[8]; xr[9]=xp[9];
            }
            u64 wp[K][2];
#pragma unroll
            for (int k = 0; k < K; k++) {
                ulonglong2 wq = *reinterpret_cast<const ulonglong2*>(&Ws[k][ci][co_th*4]);
                wp[k][0] = wq.x; wp[k][1] = wq.y;
            }
            if constexpr (STRIDE == 1) {
                u64 x0 = bc2(xr[0]), x1 = bc2(xr[1]);
#pragma unroll
                for (int j = 0; j < TPT; j++) {
                    u64 x2 = bc2(xr[j+2]);
                    fma2(acc[0][j], wp[0][0], x0); fma2(acc[1][j], wp[0][1], x0);
                    fma2(acc[0][j], wp[1][0], x1); fma2(acc[1][j], wp[1][1], x1);
                    fma2(acc[0][j], wp[2][0], x2); fma2(acc[1][j], wp[2][1], x2);
                    x0 = x1; x1 = x2;
                }
            } else {
                u64 x0 = bc2(xr[0]), x1 = bc2(xr[1]);
#pragma unroll
                for (int j = 0; j < TPT; j++) {
                    u64 x2 = bc2(xr[2*j+2]), x3 = bc2(xr[2*j+3]);
                    fma2(acc[0][j], wp[0][0], x0); fma2(acc[1][j], wp[0][1], x0);
                    fma2(acc[0][j], wp[1][0], x1); fma2(acc[1][j], wp[1][1], x1);
                    fma2(acc[0][j], wp[2][0], x2); fma2(acc[1][j], wp[2][1], x2);
                    fma2(acc[0][j], wp[3][0], x3); fma2(acc[1][j], wp[3][1], x3);
                    x0 = x2; x1 = x3;
                }
            }
        }
        __syncthreads();
    }

    float bb[4];
    {
        float4 b0 = *reinterpret_cast<const float4*>(&bias[co0+co_th*4]);
        bb[0]=b0.x; bb[1]=b0.y; bb[2]=b0.z; bb[3]=b0.w;
    }
    int tout0 = t0 + t_th*TPT;
    if (!TROUT) {
#pragma unroll
        for (int u = 0; u < 2; u++) {
            float ra[TPT], rb[TPT];
#pragma unroll
            for (int j = 0; j < TPT; j++) {
                float2 f = up2(acc[u][j]);
                float va = f.x + bb[2*u], vb = f.y + bb[2*u+1];
                ra[j] = RELU ? fmaxf(va, 0.f) : va;
                rb[j] = RELU ? fmaxf(vb, 0.f) : vb;
            }
            float* ya = &y[((size_t)b*COUT + co0+co_th*4+2*u)*Tout + tout0];
            float* yb = &y[((size_t)b*COUT + co0+co_th*4+2*u+1)*Tout + tout0];
#pragma unroll
            for (int q = 0; q < TPT/4; q++) {
                *reinterpret_cast<float4*>(ya+4*q) = make_float4(ra[4*q],ra[4*q+1],ra[4*q+2],ra[4*q+3]);
                *reinterpret_cast<float4*>(yb+4*q) = make_float4(rb[4*q],rb[4*q+1],rb[4*q+2],rb[4*q+3]);
            }
        }
    } else {
#pragma unroll
        for (int j = 0; j < TPT; j++) {
            float r[4];
#pragma unroll
            for (int u = 0; u < 2; u++) {
                float2 f = up2(acc[u][j]);
                float va = f.x + bb[2*u], vb = f.y + bb[2*u+1];
                r[2*u]   = RELU ? fmaxf(va, 0.f) : va;
                r[2*u+1] = RELU ? fmaxf(vb, 0.f) : vb;
            }
            float* yp = &y[((size_t)b*Tout + tout0+j)*COUT + co0+co_th*4];
            *reinterpret_cast<float4*>(yp) = make_float4(r[0],r[1],r[2],r[3]);
        }
    }
}

// -------- convT1d stride=2 pad=1 K=4, 512 threads, tile 128co x 128o --------
template <int CIN, int COUT>
__global__ __launch_bounds__(512, 2)
void convT1d_k(const float* __restrict__ x, const float* __restrict__ w,
               const float* __restrict__ bias, float* __restrict__ y,
               int Tin, int Tout)
{
    __shared__ float Ws[4][8][128];   // [tap][ci][co]
    __shared__ float Xs[8][68];
    int b = blockIdx.z, co0 = blockIdx.y*128, o0 = blockIdx.x*128;
    int tid = threadIdx.x, t_th = tid & 15, co_th = tid >> 4;
    int ib0 = o0/2 - 1;

    u64 acc[2][8];
#pragma unroll
    for (int u = 0; u < 2; u++)
#pragma unroll
        for (int j = 0; j < 8; j++) acc[u][j] = 0ULL;

    for (int ci0 = 0; ci0 < CIN; ci0 += 8) {
        for (int i = tid; i < 8*128*4; i += 512) {
            int co = i & 127, r = i >> 7, ci = r & 7, k = r >> 3;
            Ws[k][ci][co] = w[((size_t)(ci0+ci)*COUT + co0+co)*4 + k];
        }
        for (int i = tid; i < 8*68; i += 512) {
            int ci = i / 68, u = i - ci*68, gi = ib0 + u;
            float v = 0.f;
            if (u < 66 && gi >= 0 && gi < Tin)
                v = x[((size_t)b*CIN + ci0+ci)*Tin + gi];
            Xs[ci][u] = v;
        }
        __syncthreads();
#pragma unroll
        for (int ci = 0; ci < 8; ci++) {
            u64 xb[6];
#pragma unroll
            for (int u = 0; u < 6; u++) xb[u] = bc2(Xs[ci][t_th*4 + u]);
            u64 wp[4][2];
#pragma unroll
            for (int k = 0; k < 4; k++) {
                ulonglong2 wq = *reinterpret_cast<const ulonglong2*>(&Ws[k][ci][co_th*4]);
                wp[k][0] = wq.x; wp[k][1] = wq.y;
            }
#pragma unroll
            for (int j = 0; j < 8; j++) {
                int ua = ((j+1) >> 1) + 1, ka = (j+1) & 1;
                u64 xa = xb[ua], xv = xb[ua-1];
#pragma unroll
                for (int u = 0; u < 2; u++) {
                    fma2(acc[u][j], wp[ka][u],   xa);
                    fma2(acc[u][j], wp[ka+2][u], xv);
                }
            }
        }
        __syncthreads();
    }

    float bb[4];
    {
        float4 b0 = *reinterpret_cast<const float4*>(&bias[co0+co_th*4]);
        bb[0]=b0.x; bb[1]=b0.y; bb[2]=b0.z; bb[3]=b0.w;
    }
    int tout0 = o0 + t_th*8;
#pragma unroll
    for (int u = 0; u < 2; u++) {
        float ra[8], rb[8];
#pragma unroll
        for (int j = 0; j < 8; j++) {
            float2 f = up2(acc[u][j]);
            ra[j] = fmaxf(f.x + bb[2*u],   0.f);
            rb[j] = fmaxf(f.y + bb[2*u+1], 0.f);
        }
        float* ya = &y[((size_t)b*COUT + co0+co_th*4+2*u)*Tout + tout0];
        float* yb = &y[((size_t)b*COUT + co0+co_th*4+2*u+1)*Tout + tout0];
        *reinterpret_cast<float4*>(ya)   = make_float4(ra[0],ra[1],ra[2],ra[3]);
        *reinterpret_cast<float4*>(ya+4) = make_float4(ra[4],ra[5],ra[6],ra[7]);
        *reinterpret_cast<float4*>(yb)   = make_float4(rb[0],rb[1],rb[2],rb[3]);
        *reinterpret_cast<float4*>(yb+4) = make_float4(rb[4],rb[5],rb[6],rb[7]);
    }
}

// -------- codebook norms (double acc, one rounding) --------
__global__ void cbn_k(const float* __restrict__ cb, float* __restrict__ cbn)
{
    int k = blockIdx.x * 2 + (threadIdx.x >> 7);
    int lane = threadIdx.x & 127;
    double a = 0.0;
    for (int d = lane; d < 512; d += 128) {
        float v = cb[(size_t)k*512 + d];
        a += (double)v * (double)v;
    }
    __shared__ double s[256];
    s[threadIdx.x] = a; __syncthreads();
    for (int o = 64; o > 0; o >>= 1) {
        if (lane < o) s[threadIdx.x] += s[threadIdx.x + o];
        __syncthreads();
    }
    if (lane == 0) cbn[k] = (float)s[threadIdx.x];
}

// -------- z row norms (double acc, one rounding) --------
__global__ void zn_k(const float* __restrict__ z, float* __restrict__ zn)
{
    int b = blockIdx.x, t = threadIdx.x;
    double a = 0.0;
    for (int d = 0; d < 512; d++) {
        float v = z[((size_t)b*512 + d)*128 + t];
        a += (double)v * (double)v;
    }
    zn[b*128 + t] = (float)a;
}

// -------- VQ score: d = fl(fl(zn+cn) - 2*dot), lowest-index ties --------
__global__ __launch_bounds__(256)
void vq_score_k(const float* __restrict__ z, const float* __restrict__ cb,
                const float* __restrict__ cbn, const float* __restrict__ zn,
                float* __restrict__ bso, int* __restrict__ bio)
{
    __shared__ float Zs[8][128];
    __shared__ float Cs[8][132];
    __shared__ float RS[128][17];
    __shared__ int   RI[128][17];
    int b = blockIdx.y, kc = blockIdx.x, k0 = kc*128;
    int tid = threadIdx.x, t_th = tid & 15, k_th = tid >> 4;

    float acc[8][8];
#pragma unroll
    for (int i = 0; i < 8; i++)
#pragma unroll
        for (int j = 0; j < 8; j++) acc[i][j] = 0.f;

    for (int d0 = 0; d0 < 512; d0 += 8) {
        for (int i = tid; i < 1024; i += 256) {
            int t = i & 127, ci = i >> 7;
            Zs[ci][t] = z[((size_t)b*512 + d0+ci)*128 + t];
        }
        for (int i = tid; i < 1024; i += 256) {
            int ci = i & 7, kk = i >> 3;
            Cs[ci][kk] = cb[(size_t)(k0+kk)*512 + d0+ci];
        }
        __syncthreads();
#pragma unroll
        for (int ci = 0; ci < 8; ci++) {
            float zr[8], cr[8];
            float4 z0 = *reinterpret_cast<const float4*>(&Zs[ci][t_th*8]);
            float4 z1 = *reinterpret_cast<const float4*>(&Zs[ci][t_th*8+4]);
            float4 c0 = *reinterpret_cast<const float4*>(&Cs[ci][k_th*8]);
            float4 c1 = *reinterpret_cast<const float4*>(&Cs[ci][k_th*8+4]);
            zr[0]=z0.x; zr[1]=z0.y; zr[2]=z0.z; zr[3]=z0.w;
            zr[4]=z1.x; zr[5]=z1.y; zr[6]=z1.z; zr[7]=z1.w;
            cr[0]=c0.x; cr[1]=c0.y; cr[2]=c0.z; cr[3]=c0.w;
            cr[4]=c1.x; cr[5]=c1.y; cr[6]=c1.z; cr[7]=c1.w;
#pragma unroll
            for (int i = 0; i < 8; i++)
#pragma unroll
                for (int j = 0; j < 8; j++)
                    acc[i][j] = fmaf(zr[i], cr[j], acc[i][j]);
        }
        __syncthreads();
    }

    float znv[8];
#pragma unroll
    for (int i = 0; i < 8; i++) znv[i] = __ldg(&zn[b*128 + t_th*8 + i]);

    float bs[8]; int bi[8];
#pragma unroll
    for (int i = 0; i < 8; i++) { bs[i] = 3.0e38f; bi[i] = 0; }
#pragma unroll
    for (int j = 0; j < 8; j++) {
        int k = k0 + k_th*8 + j;
        float cn = __ldg(&cbn[k]);
#pragma unroll
        for (int i = 0; i < 8; i++) {
            float t1 = __fadd_rn(znv[i], cn);
            float s  = __fsub_rn(t1, __fmul_rn(2.f, acc[i][j]));
            if (s < bs[i]) { bs[i] = s; bi[i] = k; }
        }
    }
#pragma unroll
    for (int i = 0; i < 8; i++) {
        RS[t_th*8+i][k_th] = bs[i];
        RI[t_th*8+i][k_th] = bi[i];
    }
    __syncthreads();
    if (tid < 128) {
        float best = RS[tid][0];
        int bidx = RI[tid][0];
        for (int jj = 1; jj < 16; jj++) {
            float s = RS[tid][jj]; int ii = RI[tid][jj];
            if (s < best || (s == best && ii < bidx)) { best = s; bidx = ii; }
        }
        bso[((size_t)b*4 + kc)*128 + tid] = best;
        bio[((size_t)b*4 + kc)*128 + tid] = bidx;
    }
}

__global__ void vq_combine_k(const float* __restrict__ bso, const int* __restrict__ bio,
                             int* __restrict__ idx, float* __restrict__ outIdx)
{
    int n = blockIdx.x*256 + threadIdx.x;
    if (n >= 64*128) return;
    int b = n >> 7, t = n & 127;
    float best = bso[(size_t)b*4*128 + t];
    int bi = bio[(size_t)b*4*128 + t];
    for (int c = 1; c < 4; c++) {
        float s = bso[((size_t)b*4 + c)*128 + t];
        int ii  = bio[((size_t)b*4 + c)*128 + t];
        if (s < best || (s == best && ii < bi)) { best = s; bi = ii; }
    }
    idx[n] = bi;
    outIdx[n] = (float)bi;
}

__global__ void vq_gather_k(const float* __restrict__ cb, const int* __restrict__ idx,
                            const float* __restrict__ z,
                            float* __restrict__ zq_st, float* __restrict__ zq_raw)
{
    int b = blockIdx.x;
    __shared__ int sidx[128];
    if (threadIdx.x < 128) sidx[threadIdx.x] = idx[b*128 + threadIdx.x];
    __syncthreads();
    int t = threadIdx.x & 127, d0 = threadIdx.x >> 7;
    for (int d = d0; d < 512; d += 2) {
        size_t o = ((size_t)b*512 + d)*128 + t;
        float c  = cb[(size_t)sidx[t]*512 + d];
        float zv = z[o];
        zq_raw[o] = c;
        zq_st[o]  = __fadd_rn(zv, __fsub_rn(c, zv));
    }
}

// -------- loss = 0.25 * mean((z-zq_raw)^2), deterministic 2-pass --------
__global__ void loss_partial_k(const float* __restrict__ z, const float* __restrict__ zq,
                               double* __restrict__ part)
{
    const int N = 64*512*128;
    double a = 0.0;
    for (int i = blockIdx.x*blockDim.x + threadIdx.x; i < N; i += gridDim.x*blockDim.x) {
        float d = __fsub_rn(z[i], zq[i]);
        a += (double)d * (double)d;
    }
    __shared__ double s[256];
    s[threadIdx.x] = a; __syncthreads();
    for (int o = 128; o > 0; o >>= 1) {
        if (threadIdx.x < o) s[threadIdx.x] += s[threadIdx.x+o];
        __syncthreads();
    }
    if (threadIdx.x == 0) part[blockIdx.x] = s[0];
}

__global__ void loss_final_k(const double* __restrict__ part, float* __restrict__ out)
{
    __shared__ double s[256];
    s[threadIdx.x] = part[threadIdx.x]; __syncthreads();
    for (int o = 128; o > 0; o >>= 1) {
        if (threadIdx.x < o) s[threadIdx.x] += s[threadIdx.x+o];
        __syncthreads();
    }
    if (threadIdx.x == 0)
        *out = 0.25f * (float)(s[0] / (double)(64*512*128));
}

extern "C" void kernel_launch(void* const* d_in, const int* in_sizes, int n_in,
                              void* d_out, int out_size)
{
    const float* x    = (const float*)d_in[0];
    const float* ew1  = (const float*)d_in[1];  const float* eb1 = (const float*)d_in[2];
    const float* ew2  = (const float*)d_in[3];  const float* eb2 = (const float*)d_in[4];
    const float* ew3  = (const float*)d_in[5];  const float* eb3 = (const float*)d_in[6];
    const float* ew4  = (const float*)d_in[7];  const float* eb4 = (const float*)d_in[8];
    const float* ew5  = (const float*)d_in[9];  const float* eb5 = (const float*)d_in[10];
    const float* cb   = (const float*)d_in[11];
    const float* dw1  = (const float*)d_in[12]; const float* db1 = (const float*)d_in[13];
    const float* dwt2 = (const float*)d_in[14]; const float* dbt2= (const float*)d_in[15];
    const float* dw3  = (const float*)d_in[16]; const float* db3 = (const float*)d_in[17];
    const float* dwt4 = (const float*)d_in[18]; const float* dbt4= (const float*)d_in[19];
    const float* dw5  = (const float*)d_in[20]; const float* db5 = (const float*)d_in[21];
    float* out = (float*)d_out;

    float *xt, *h1, *h2, *h3, *h4, *z, *zq, *zqr, *g1, *g2, *g3, *g4, *cbn, *zn, *bs;
    int *bi, *idx; double* part;
    cudaGetSymbolAddress((void**)&xt, g_xt);   cudaGetSymbolAddress((void**)&h1, g_h1);
    cudaGetSymbolAddress((void**)&h2, g_h2);   cudaGetSymbolAddress((void**)&h3, g_h3);
    cudaGetSymbolAddress((void**)&h4, g_h4);   cudaGetSymbolAddress((void**)&z,  g_z);
    cudaGetSymbolAddress((void**)&zq, g_zq);   cudaGetSymbolAddress((void**)&zqr, g_zqr);
    cudaGetSymbolAddress((void**)&g1, g_g1);   cudaGetSymbolAddress((void**)&g2, g_g2);
    cudaGetSymbolAddress((void**)&g3, g_g3);   cudaGetSymbolAddress((void**)&g4, g_g4);
    cudaGetSymbolAddress((void**)&cbn, g_cbn); cudaGetSymbolAddress((void**)&zn, g_zn);
    cudaGetSymbolAddress((void**)&bs, g_bs);   cudaGetSymbolAddress((void**)&bi, g_bi);
    cudaGetSymbolAddress((void**)&idx, g_idx); cudaGetSymbolAddress((void**)&part, g_part);

    // encoder
    transpose_in_k<<<dim3(16,8,64), dim3(32,8)>>>(x, xt);
    conv1d_k<256,256,3,1,128,true,false><<<dim3(4,2,64),512>>>(xt, ew1, eb1, h1, 512, 512);
    conv1d_k<256,256,4,2, 64,true,false><<<dim3(4,2,64),512>>>(h1, ew2, eb2, h2, 512, 256);
    conv1d_k<256,512,3,1,128,true,false><<<dim3(2,4,64),512>>>(h2, ew3, eb3, h3, 256, 256);
    conv1d_k<512,512,4,2, 64,true,false><<<dim3(2,4,64),512>>>(h3, ew4, eb4, h4, 256, 128);
    conv1d_k<512,512,3,1,128,false,false><<<dim3(1,4,64),512>>>(h4, ew5, eb5, z, 128, 128);
    // VQ
    cbn_k<<<256,256>>>(cb, cbn);
    zn_k<<<64,128>>>(z, zn);
    vq_score_k<<<dim3(4,64),256>>>(z, cb, cbn, zn, bs, bi);
    vq_combine_k<<<32,256>>>(bs, bi, idx, out + 64*512*256);
    vq_gather_k<<<64,256>>>(cb, idx, z, zq, zqr);
    loss_partial_k<<<256,256>>>(z, zqr, part);
    loss_final_k<<<1,256>>>(part, out + 64*512*256 + 64*128);
    // decoder
    conv1d_k<512,512,3,1,128,true,false><<<dim3(1,4,64),512>>>(zq, dw1, db1, g1, 128, 128);
    convT1d_k<512,512><<<dim3(2,4,64),512>>>(g1, dwt2, dbt2, g2, 128, 256);
    conv1d_k<512,256,3,1,128,true,false><<<dim3(2,2,64),512>>>(g2, dw3, db3, g3, 256, 256);
    convT1d_k<256,256><<<dim3(4,2,64),512>>>(g3, dwt4, dbt4, g4, 256, 512);
    conv1d_k<256,256,3,1,128,false,true><<<dim3(4,2,64),512>>>(g4, dw5, db5, out, 512, 512);
}

// round 6
// speedup vs baseline: 1.8893x; 1.8893x over previous
#include <cuda_runtime.h>

typedef unsigned long long u64;
typedef unsigned int u32;

__device__ __forceinline__ u64 bc2(float v){ u64 r; asm("mov.b64 %0, {%1,%1};":"=l"(r):"f"(v)); return r; }
__device__ __forceinline__ void fma2(u64& c, u64 a, u64 b){ asm("fma.rn.f32x2 %0, %1, %2, %0;":"+l"(c):"l"(a),"l"(b)); }
__device__ __forceinline__ float2 up2(u64 v){ float lo,hi; asm("mov.b64 {%0,%1}, %2;":"=f"(lo),"=f"(hi):"l"(v)); return make_float2(lo,hi); }
__device__ __forceinline__ u32 sptr(const void* p){ return (u32)__cvta_generic_to_shared(p); }
__device__ __forceinline__ void cp16z(u32 dst, const float* src, bool ok){
    int sz = ok ? 16 : 0;
    asm volatile("cp.async.cg.shared.global [%0], [%1], 16, %2;"::"r"(dst),"l"(src),"r"(sz));
}
__device__ __forceinline__ void cpcommit(){ asm volatile("cp.async.commit_group;"); }
__device__ __forceinline__ void cpwait1(){ asm volatile("cp.async.wait_group 1;"); }

// -------- scratch (no allocation allowed) --------
__device__ float g_xt[64*256*512];
__device__ float g_h1[64*256*512];
__device__ float g_h2[64*256*256];
__device__ float g_h3[64*512*256];
__device__ float g_h4[64*512*128];
__device__ float g_z [64*512*128];
__device__ float g_zq[64*512*128];
__device__ float g_zqr[64*512*128];
__device__ float g_g1[64*512*128];
__device__ float g_g2[64*512*256];
__device__ float g_g3[64*256*256];
__device__ float g_g4[64*256*512];
__device__ float g_wt[4*512*512];      // transposed weights [k][ci][co]
__device__ float g_cbn[512];
__device__ float g_zn[64*128];
__device__ float g_bs[64*4*128];
__device__ int   g_bi[64*4*128];
__device__ int   g_idx[64*128];
__device__ double g_part[256];

// -------- weight re-layout: wt[(k*CIN+ci)*COUT+co] --------
__global__ void wtr_k(const float* __restrict__ w, float* __restrict__ wt,
                      int CIN, int COUT, int K, int isT)
{
    int i = blockIdx.x*256 + threadIdx.x;
    if (i >= CIN*COUT*K) return;
    int co = i % COUT, r = i / COUT, ci = r % CIN, k = r / CIN;
    wt[i] = isT ? w[((size_t)ci*COUT + co)*K + k]     // convT: w[I][O][K]
                : w[((size_t)co*CIN + ci)*K + k];     // conv : w[O][I][K]
}

// -------- [B,T,F] -> [B,F,T] --------
__global__ void transpose_in_k(const float* __restrict__ x, float* __restrict__ xt)
{
    __shared__ float tile[32][33];
    int b = blockIdx.z, t0 = blockIdx.x*32, f0 = blockIdx.y*32;
    int tx = threadIdx.x, ty = threadIdx.y;
#pragma unroll
    for (int r = 0; r < 32; r += 8)
        tile[ty+r][tx] = x[((size_t)b*512 + (t0+ty+r))*256 + f0+tx];
    __syncthreads();
#pragma unroll
    for (int r = 0; r < 32; r += 8)
        xt[((size_t)b*256 + (f0+ty+r))*512 + t0+tx] = tile[tx][ty+r];
}

// -------- conv1d, 256 thr, 128co x 128t tile, double-buffered cp.async --------
template <int CIN, int COUT, int K, int STRIDE, bool RELU, bool TROUT>
__global__ __launch_bounds__(256, 2)
void conv1d_k(const float* __restrict__ x, const float* __restrict__ wt,
              const float* __restrict__ bias, float* __restrict__ y,
              int Tin, int Tout)
{
    constexpr int XPAD = (STRIDE==1) ? 136 : 264;
    constexpr int NIT  = CIN/8;
    constexpr int WST  = K*8*128;
    constexpr int XST  = 8*XPAD;
    extern __shared__ float sm[];
    float* Wb = sm;
    float* Xb = sm + 2*WST;

    int b = blockIdx.z, co0 = blockIdx.y*128, t0 = blockIdx.x*128;
    int tid = threadIdx.x, t_th = tid & 15, co_th = tid >> 4;
    int gbase = t0*STRIDE - 4;

    u64 acc[4][8];
#pragma unroll
    for (int u = 0; u < 4; u++)
#pragma unroll
        for (int j = 0; j < 8; j++) acc[u][j] = 0ULL;

    auto fill = [&](int s, int ci0){
        float* W = Wb + s*WST;
#pragma unroll
        for (int i = tid; i < K*8*32; i += 256) {
            int q = i & 31, r = i >> 5;        // r = k*8+ci
            int ci = r & 7, k = r >> 3;
            cp16z(sptr(W + r*128 + q*4),
                  wt + ((size_t)(k*CIN + ci0+ci))*COUT + co0 + q*4, true);
        }
        float* X = Xb + s*XST;
#pragma unroll
        for (int i = tid; i < 8*(XPAD/4); i += 256) {
            int ci = i / (XPAD/4), c = i % (XPAD/4);
            int gt = gbase + 4*c;
            bool ok = (gt >= 0) && (gt < Tin);
            const float* src = x + ((size_t)b*CIN + ci0+ci)*Tin + (ok ? gt : 0);
            cp16z(sptr(X + ci*XPAD + 4*c), src, ok);
        }
    };

    fill(0, 0); cpcommit();
#pragma unroll 1
    for (int it = 0; it < NIT; it++) {
        int cur = it & 1;
        if (it+1 < NIT) fill(cur^1, (it+1)*8);
        cpcommit();
        cpwait1();
        __syncthreads();
        const float* W = Wb + cur*WST;
        const float* X = Xb + cur*XST;
#pragma unroll
        for (int ci = 0; ci < 8; ci++) {
            constexpr int NXL = (STRIDE==1) ? 4 : 6;
            float xr[NXL*4];
            const float* xp = X + ci*XPAD + t_th*8*STRIDE;
#pragma unroll
            for (int q = 0; q < NXL; q++) {
                float4 v = *reinterpret_cast<const float4*>(xp + 4*q);
                xr[4*q]=v.x; xr[4*q+1]=v.y; xr[4*q+2]=v.z; xr[4*q+3]=v.w;
            }
            u64 wp[K][4];
#pragma unroll
            for (int k = 0; k < K; k++) {
                const ulonglong2* wq = reinterpret_cast<const ulonglong2*>(W + (k*8+ci)*128 + co_th*8);
                ulonglong2 a = wq[0], bq = wq[1];
                wp[k][0]=a.x; wp[k][1]=a.y; wp[k][2]=bq.x; wp[k][3]=bq.y;
            }
            if constexpr (STRIDE==1) {
                u64 x0 = bc2(xr[3]), x1 = bc2(xr[4]);
#pragma unroll
                for (int j = 0; j < 8; j++) {
                    u64 x2 = bc2(xr[j+5]);
#pragma unroll
                    for (int u = 0; u < 4; u++) fma2(acc[u][j], wp[0][u], x0);
#pragma unroll
                    for (int u = 0; u < 4; u++) fma2(acc[u][j], wp[1][u], x1);
#pragma unroll
                    for (int u = 0; u < 4; u++) fma2(acc[u][j], wp[2][u], x2);
                    x0 = x1; x1 = x2;
                }
            } else {
                u64 x0 = bc2(xr[3]), x1 = bc2(xr[4]);
#pragma unroll
                for (int j = 0; j < 8; j++) {
                    u64 x2 = bc2(xr[2*j+5]), x3 = bc2(xr[2*j+6]);
#pragma unroll
                    for (int u = 0; u < 4; u++) fma2(acc[u][j], wp[0][u], x0);
#pragma unroll
                    for (int u = 0; u < 4; u++) fma2(acc[u][j], wp[1][u], x1);
#pragma unroll
                    for (int u = 0; u < 4; u++) fma2(acc[u][j], wp[2][u], x2);
#pragma unroll
                    for (int u = 0; u < 4; u++) fma2(acc[u][j], wp[3][u], x3);
                    x0 = x2; x1 = x3;
                }
            }
        }
        __syncthreads();
    }

    float bb[8];
    {
        float4 b0 = *reinterpret_cast<const float4*>(&bias[co0+co_th*8]);
        float4 b1 = *reinterpret_cast<const float4*>(&bias[co0+co_th*8+4]);
        bb[0]=b0.x; bb[1]=b0.y; bb[2]=b0.z; bb[3]=b0.w;
        bb[4]=b1.x; bb[5]=b1.y; bb[6]=b1.z; bb[7]=b1.w;
    }
    int tout0 = t0 + t_th*8;
    if (!TROUT) {
#pragma unroll
        for (int u = 0; u < 4; u++) {
            float ra[8], rb[8];
#pragma unroll
            for (int j = 0; j < 8; j++) {
                float2 f = up2(acc[u][j]);
                float va = f.x + bb[2*u], vb = f.y + bb[2*u+1];
                ra[j] = RELU ? fmaxf(va, 0.f) : va;
                rb[j] = RELU ? fmaxf(vb, 0.f) : vb;
            }
            float* ya = &y[((size_t)b*COUT + co0+co_th*8+2*u)*Tout + tout0];
            float* yb = &y[((size_t)b*COUT + co0+co_th*8+2*u+1)*Tout + tout0];
            *reinterpret_cast<float4*>(ya)   = make_float4(ra[0],ra[1],ra[2],ra[3]);
            *reinterpret_cast<float4*>(ya+4) = make_float4(ra[4],ra[5],ra[6],ra[7]);
            *reinterpret_cast<float4*>(yb)   = make_float4(rb[0],rb[1],rb[2],rb[3]);
            *reinterpret_cast<float4*>(yb+4) = make_float4(rb[4],rb[5],rb[6],rb[7]);
        }
    } else {
#pragma unroll
        for (int j = 0; j < 8; j++) {
            float r[8];
#pragma unroll
            for (int u = 0; u < 4; u++) {
                float2 f = up2(acc[u][j]);
                float va = f.x + bb[2*u], vb = f.y + bb[2*u+1];
                r[2*u]   = RELU ? fmaxf(va, 0.f) : va;
                r[2*u+1] = RELU ? fmaxf(vb, 0.f) : vb;
            }
            float* yp = &y[((size_t)b*Tout + tout0+j)*COUT + co0+co_th*8];
            *reinterpret_cast<float4*>(yp)   = make_float4(r[0],r[1],r[2],r[3]);
            *reinterpret_cast<float4*>(yp+4) = make_float4(r[4],r[5],r[6],r[7]);
        }
    }
}

// -------- convT1d s2 p1 K4, 256 thr, 128co x 128o, double-buffered --------
template <int CIN, int COUT>
__global__ __launch_bounds__(256, 2)
void convT1d_k(const float* __restrict__ x, const float* __restrict__ wt,
               const float* __restrict__ bias, float* __restrict__ y,
               int Tin, int Tout)
{
    constexpr int XPAD = 72;
    constexpr int NIT  = CIN/8;
    constexpr int WST  = 4*8*128;
    constexpr int XST  = 8*XPAD;
    extern __shared__ float sm[];
    float* Wb = sm;
    float* Xb = sm + 2*WST;

    int b = blockIdx.z, co0 = blockIdx.y*128, o0 = blockIdx.x*128;
    int tid = threadIdx.x, t_th = tid & 15, co_th = tid >> 4;
    int gbase = o0/2 - 4;

    u64 acc[4][8];
#pragma unroll
    for (int u = 0; u < 4; u++)
#pragma unroll
        for (int j = 0; j < 8; j++) acc[u][j] = 0ULL;

    auto fill = [&](int s, int ci0){
        float* W = Wb + s*WST;
#pragma unroll
        for (int i = tid; i < 4*8*32; i += 256) {
            int q = i & 31, r = i >> 5;
            int ci = r & 7, k = r >> 3;
            cp16z(sptr(W + r*128 + q*4),
                  wt + ((size_t)(k*CIN + ci0+ci))*COUT + co0 + q*4, true);
        }
        float* X = Xb + s*XST;
#pragma unroll
        for (int i = tid; i < 8*(XPAD/4); i += 256) {
            int ci = i / (XPAD/4), c = i % (XPAD/4);
            int gi = gbase + 4*c;
            bool ok = (gi >= 0) && (gi < Tin);
            const float* src = x + ((size_t)b*CIN + ci0+ci)*Tin + (ok ? gi : 0);
            cp16z(sptr(X + ci*XPAD + 4*c), src, ok);
        }
    };

    fill(0, 0); cpcommit();
#pragma unroll 1
    for (int it = 0; it < NIT; it++) {
        int cur = it & 1;
        if (it+1 < NIT) fill(cur^1, (it+1)*8);
        cpcommit();
        cpwait1();
        __syncthreads();
        const float* W = Wb + cur*WST;
        const float* X = Xb + cur*XST;
#pragma unroll
        for (int ci = 0; ci < 8; ci++) {
            float xr[12];
            const float* xp = X + ci*XPAD + t_th*4;
#pragma unroll
            for (int q = 0; q < 3; q++) {
                float4 v = *reinterpret_cast<const float4*>(xp + 4*q);
                xr[4*q]=v.x; xr[4*q+1]=v.y; xr[4*q+2]=v.z; xr[4*q+3]=v.w;
            }
            u64 xb[6];
#pragma unroll
            for (int u = 0; u < 6; u++) xb[u] = bc2(xr[u+3]);
            u64 wp[4][4];
#pragma unroll
            for (int k = 0; k < 4; k++) {
                const ulonglong2* wq = reinterpret_cast<const ulonglong2*>(W + (k*8+ci)*128 + co_th*8);
                ulonglong2 a = wq[0], bq = wq[1];
                wp[k][0]=a.x; wp[k][1]=a.y; wp[k][2]=bq.x; wp[k][3]=bq.y;
            }
#pragma unroll
            for (int j = 0; j < 8; j++) {
                int ua = ((j+1) >> 1) + 1, ka = (j+1) & 1;
                u64 xa = xb[ua], xv = xb[ua-1];
#pragma unroll
                for (int u = 0; u < 4; u++) {
                    fma2(acc[u][j], wp[ka][u],   xa);
                    fma2(acc[u][j], wp[ka+2][u], xv);
                }
            }
        }
        __syncthreads();
    }

    float bb[8];
    {
        float4 b0 = *reinterpret_cast<const float4*>(&bias[co0+co_th*8]);
        float4 b1 = *reinterpret_cast<const float4*>(&bias[co0+co_th*8+4]);
        bb[0]=b0.x; bb[1]=b0.y; bb[2]=b0.z; bb[3]=b0.w;
        bb[4]=b1.x; bb[5]=b1.y; bb[6]=b1.z; bb[7]=b1.w;
    }
    int tout0 = o0 + t_th*8;
#pragma unroll
    for (int u = 0; u < 4; u++) {
        float ra[8], rb[8];
#pragma unroll
        for (int j = 0; j < 8; j++) {
            float2 f = up2(acc[u][j]);
            ra[j] = fmaxf(f.x + bb[2*u],   0.f);
            rb[j] = fmaxf(f.y + bb[2*u+1], 0.f);
        }
        float* ya = &y[((size_t)b*COUT + co0+co_th*8+2*u)*Tout + tout0];
        float* yb = &y[((size_t)b*COUT + co0+co_th*8+2*u+1)*Tout + tout0];
        *reinterpret_cast<float4*>(ya)   = make_float4(ra[0],ra[1],ra[2],ra[3]);
        *reinterpret_cast<float4*>(ya+4) = make_float4(ra[4],ra[5],ra[6],ra[7]);
        *reinterpret_cast<float4*>(yb)   = make_float4(rb[0],rb[1],rb[2],rb[3]);
        *reinterpret_cast<float4*>(yb+4) = make_float4(rb[4],rb[5],rb[6],rb[7]);
    }
}

// -------- codebook norms --------
__global__ void cbn_k(const float* __restrict__ cb, float* __restrict__ cbn)
{
    int k = blockIdx.x * 2 + (threadIdx.x >> 7);
    int lane = threadIdx.x & 127;
    double a = 0.0;
    for (int d = lane; d < 512; d += 128) {
        float v = cb[(size_t)k*512 + d];
        a += (double)v * (double)v;
    }
    __shared__ double s[256];
    s[threadIdx.x] = a; __syncthreads();
    for (int o = 64; o > 0; o >>= 1) {
        if (lane < o) s[threadIdx.x] += s[threadIdx.x + o];
        __syncthreads();
    }
    if (lane == 0) cbn[k] = (float)s[threadIdx.x];
}

// -------- z row norms --------
__global__ void zn_k(const float* __restrict__ z, float* __restrict__ zn)
{
    int b = blockIdx.x, t = threadIdx.x;
    double a = 0.0;
    for (int d = 0; d < 512; d++) {
        float v = z[((size_t)b*512 + d)*128 + t];
        a += (double)v * (double)v;
    }
    zn[b*128 + t] = (float)a;
}

// -------- VQ score (UNCHANGED — numerics-critical) --------
__global__ __launch_bounds__(256)
void vq_score_k(const float* __restrict__ z, const float* __restrict__ cb,
                const float* __restrict__ cbn, const float* __restrict__ zn,
                float* __restrict__ bso, int* __restrict__ bio)
{
    __shared__ float Zs[8][128];
    __shared__ float Cs[8][132];
    __shared__ float RS[128][17];
    __shared__ int   RI[128][17];
    int b = blockIdx.y, kc = blockIdx.x, k0 = kc*128;
    int tid = threadIdx.x, t_th = tid & 15, k_th = tid >> 4;

    float acc[8][8];
#pragma unroll
    for (int i = 0; i < 8; i++)
#pragma unroll
        for (int j = 0; j < 8; j++) acc[i][j] = 0.f;

    for (int d0 = 0; d0 < 512; d0 += 8) {
        for (int i = tid; i < 1024; i += 256) {
            int t = i & 127, ci = i >> 7;
            Zs[ci][t] = z[((size_t)b*512 + d0+ci)*128 + t];
        }
        for (int i = tid; i < 1024; i += 256) {
            int ci = i & 7, kk = i >> 3;
            Cs[ci][kk] = cb[(size_t)(k0+kk)*512 + d0+ci];
        }
        __syncthreads();
#pragma unroll
        for (int ci = 0; ci < 8; ci++) {
            float zr[8], cr[8];
            float4 z0 = *reinterpret_cast<const float4*>(&Zs[ci][t_th*8]);
            float4 z1 = *reinterpret_cast<const float4*>(&Zs[ci][t_th*8+4]);
            float4 c0 = *reinterpret_cast<const float4*>(&Cs[ci][k_th*8]);
            float4 c1 = *reinterpret_cast<const float4*>(&Cs[ci][k_th*8+4]);
            zr[0]=z0.x; zr[1]=z0.y; zr[2]=z0.z; zr[3]=z0.w;
            zr[4]=z1.x; zr[5]=z1.y; zr[6]=z1.z; zr[7]=z1.w;
            cr[0]=c0.x; cr[1]=c0.y; cr[2]=c0.z; cr[3]=c0.w;
            cr[4]=c1.x; cr[5]=c1.y; cr[6]=c1.z; cr[7]=c1.w;
#pragma unroll
            for (int i = 0; i < 8; i++)
#pragma unroll
                for (int j = 0; j < 8; j++)
                    acc[i][j] = fmaf(zr[i], cr[j], acc[i][j]);
        }
        __syncthreads();
    }

    float znv[8];
#pragma unroll
    for (int i = 0; i < 8; i++) znv[i] = __ldg(&zn[b*128 + t_th*8 + i]);

    float bs[8]; int bi[8];
#pragma unroll
    for (int i = 0; i < 8; i++) { bs[i] = 3.0e38f; bi[i] = 0; }
#pragma unroll
    for (int j = 0; j < 8; j++) {
        int k = k0 + k_th*8 + j;
        float cn = __ldg(&cbn[k]);
#pragma unroll
        for (int i = 0; i < 8; i++) {
            float t1 = __fadd_rn(znv[i], cn);
            float s  = __fsub_rn(t1, __fmul_rn(2.f, acc[i][j]));
            if (s < bs[i]) { bs[i] = s; bi[i] = k; }
        }
    }
#pragma unroll
    for (int i = 0; i < 8; i++) {
        RS[t_th*8+i][k_th] = bs[i];
        RI[t_th*8+i][k_th] = bi[i];
    }
    __syncthreads();
    if (tid < 128) {
        float best = RS[tid][0];
        int bidx = RI[tid][0];
        for (int jj = 1; jj < 16; jj++) {
            float s = RS[tid][jj]; int ii = RI[tid][jj];
            if (s < best || (s == best && ii < bidx)) { best = s; bidx = ii; }
        }
        bso[((size_t)b*4 + kc)*128 + tid] = best;
        bio[((size_t)b*4 + kc)*128 + tid] = bidx;
    }
}

__global__ void vq_combine_k(const float* __restrict__ bso, const int* __restrict__ bio,
                             int* __restrict__ idx, float* __restrict__ outIdx)
{
    int n = blockIdx.x*256 + threadIdx.x;
    if (n >= 64*128) return;
    int b = n >> 7, t = n & 127;
    float best = bso[(size_t)b*4*128 + t];
    int bi = bio[(size_t)b*4*128 + t];
    for (int c = 1; c < 4; c++) {
        float s = bso[((size_t)b*4 + c)*128 + t];
        int ii  = bio[((size_t)b*4 + c)*128 + t];
        if (s < best || (s == best && ii < bi)) { best = s; bi = ii; }
    }
    idx[n] = bi;
    outIdx[n] = (float)bi;
}

__global__ void vq_gather_k(const float* __restrict__ cb, const int* __restrict__ idx,
                            const float* __restrict__ z,
                            float* __restrict__ zq_st, float* __restrict__ zq_raw)
{
    int b = blockIdx.x;
    __shared__ int sidx[128];
    if (threadIdx.x < 128) sidx[threadIdx.x] = idx[b*128 + threadIdx.x];
    __syncthreads();
    int t = threadIdx.x & 127, d0 = threadIdx.x >> 7;
    for (int d = d0; d < 512; d += 2) {
        size_t o = ((size_t)b*512 + d)*128 + t;
        float c  = cb[(size_t)sidx[t]*512 + d];
        float zv = z[o];
        zq_raw[o] = c;
        zq_st[o]  = __fadd_rn(zv, __fsub_rn(c, zv));
    }
}

__global__ void loss_partial_k(const float* __restrict__ z, const float* __restrict__ zq,
                               double* __restrict__ part)
{
    const int N = 64*512*128;
    double a = 0.0;
    for (int i = blockIdx.x*blockDim.x + threadIdx.x; i < N; i += gridDim.x*blockDim.x) {
        float d = __fsub_rn(z[i], zq[i]);
        a += (double)d * (double)d;
    }
    __shared__ double s[256];
    s[threadIdx.x] = a; __syncthreads();
    for (int o = 128; o > 0; o >>= 1) {
        if (threadIdx.x < o) s[threadIdx.x] += s[threadIdx.x+o];
        __syncthreads();
    }
    if (threadIdx.x == 0) part[blockIdx.x] = s[0];
}

__global__ void loss_final_k(const double* __restrict__ part, float* __restrict__ out)
{
    __shared__ double s[256];
    s[threadIdx.x] = part[threadIdx.x]; __syncthreads();
    for (int o = 128; o > 0; o >>= 1) {
        if (threadIdx.x < o) s[threadIdx.x] += s[threadIdx.x+o];
        __syncthreads();
    }
    if (threadIdx.x == 0)
        *out = 0.25f * (float)(s[0] / (double)(64*512*128));
}

extern "C" void kernel_launch(void* const* d_in, const int* in_sizes, int n_in,
                              void* d_out, int out_size)
{
    const float* x    = (const float*)d_in[0];
    const float* ew1  = (const float*)d_in[1];  const float* eb1 = (const float*)d_in[2];
    const float* ew2  = (const float*)d_in[3];  const float* eb2 = (const float*)d_in[4];
    const float* ew3  = (const float*)d_in[5];  const float* eb3 = (const float*)d_in[6];
    const float* ew4  = (const float*)d_in[7];  const float* eb4 = (const float*)d_in[8];
    const float* ew5  = (const float*)d_in[9];  const float* eb5 = (const float*)d_in[10];
    const float* cb   = (const float*)d_in[11];
    const float* dw1  = (const float*)d_in[12]; const float* db1 = (const float*)d_in[13];
    const float* dwt2 = (const float*)d_in[14]; const float* dbt2= (const float*)d_in[15];
    const float* dw3  = (const float*)d_in[16]; const float* db3 = (const float*)d_in[17];
    const float* dwt4 = (const float*)d_in[18]; const float* dbt4= (const float*)d_in[19];
    const float* dw5  = (const float*)d_in[20]; const float* db5 = (const float*)d_in[21];
    float* out = (float*)d_out;

    float *xt, *h1, *h2, *h3, *h4, *z, *zq, *zqr, *g1, *g2, *g3, *g4, *wt, *cbn, *zn, *bs;
    int *bi, *idx; double* part;
    cudaGetSymbolAddress((void**)&xt, g_xt);   cudaGetSymbolAddress((void**)&h1, g_h1);
    cudaGetSymbolAddress((void**)&h2, g_h2);   cudaGetSymbolAddress((void**)&h3, g_h3);
    cudaGetSymbolAddress((void**)&h4, g_h4);   cudaGetSymbolAddress((void**)&z,  g_z);
    cudaGetSymbolAddress((void**)&zq, g_zq);   cudaGetSymbolAddress((void**)&zqr, g_zqr);
    cudaGetSymbolAddress((void**)&g1, g_g1);   cudaGetSymbolAddress((void**)&g2, g_g2);
    cudaGetSymbolAddress((void**)&g3, g_g3);   cudaGetSymbolAddress((void**)&g4, g_g4);
    cudaGetSymbolAddress((void**)&wt, g_wt);
    cudaGetSymbolAddress((void**)&cbn, g_cbn); cudaGetSymbolAddress((void**)&zn, g_zn);
    cudaGetSymbolAddress((void**)&bs, g_bs);   cudaGetSymbolAddress((void**)&bi, g_bi);
    cudaGetSymbolAddress((void**)&idx, g_idx); cudaGetSymbolAddress((void**)&part, g_part);

    const int SM1 = (2*3*8*128 + 2*8*136)*4;   // 33280
    const int SM2 = (2*4*8*128 + 2*8*264)*4;   // 49664
    const int SMT = (2*4*8*128 + 2*8*72)*4;    // 37376

    cudaFuncSetAttribute(conv1d_k<256,256,3,1,true,false>,  cudaFuncAttributeMaxDynamicSharedMemorySize, SM1);
    cudaFuncSetAttribute(conv1d_k<256,256,4,2,true,false>,  cudaFuncAttributeMaxDynamicSharedMemorySize, SM2);
    cudaFuncSetAttribute(conv1d_k<256,512,3,1,true,false>,  cudaFuncAttributeMaxDynamicSharedMemorySize, SM1);
    cudaFuncSetAttribute(conv1d_k<512,512,4,2,true,false>,  cudaFuncAttributeMaxDynamicSharedMemorySize, SM2);
    cudaFuncSetAttribute(conv1d_k<512,512,3,1,false,false>, cudaFuncAttributeMaxDynamicSharedMemorySize, SM1);
    cudaFuncSetAttribute(conv1d_k<512,512,3,1,true,false>,  cudaFuncAttributeMaxDynamicSharedMemorySize, SM1);
    cudaFuncSetAttribute(conv1d_k<512,256,3,1,true,false>,  cudaFuncAttributeMaxDynamicSharedMemorySize, SM1);
    cudaFuncSetAttribute(conv1d_k<256,256,3,1,false,true>,  cudaFuncAttributeMaxDynamicSharedMemorySize, SM1);
    cudaFuncSetAttribute(convT1d_k<512,512>, cudaFuncAttributeMaxDynamicSharedMemorySize, SMT);
    cudaFuncSetAttribute(convT1d_k<256,256>, cudaFuncAttributeMaxDynamicSharedMemorySize, SMT);

    // encoder
    transpose_in_k<<<dim3(16,8,64), dim3(32,8)>>>(x, xt);
    wtr_k<<<(256*256*3+255)/256,256>>>(ew1, wt, 256, 256, 3, 0);
    conv1d_k<256,256,3,1,true,false><<<dim3(4,2,64),256,SM1>>>(xt, wt, eb1, h1, 512, 512);
    wtr_k<<<(256*256*4+255)/256,256>>>(ew2, wt, 256, 256, 4, 0);
    conv1d_k<256,256,4,2,true,false><<<dim3(2,2,64),256,SM2>>>(h1, wt, eb2, h2, 512, 256);
    wtr_k<<<(256*512*3+255)/256,256>>>(ew3, wt, 256, 512, 3, 0);
    conv1d_k<256,512,3,1,true,false><<<dim3(2,4,64),256,SM1>>>(h2, wt, eb3, h3, 256, 256);
    wtr_k<<<(512*512*4+255)/256,256>>>(ew4, wt, 512, 512, 4, 0);
    conv1d_k<512,512,4,2,true,false><<<dim3(1,4,64),256,SM2>>>(h3, wt, eb4, h4, 256, 128);
    wtr_k<<<(512*512*3+255)/256,256>>>(ew5, wt, 512, 512, 3, 0);
    conv1d_k<512,512,3,1,false,false><<<dim3(1,4,64),256,SM1>>>(h4, wt, eb5, z, 128, 128);
    // VQ
    cbn_k<<<256,256>>>(cb, cbn);
    zn_k<<<64,128>>>(z, zn);
    vq_score_k<<<dim3(4,64),256>>>(z, cb, cbn, zn, bs, bi);
    vq_combine_k<<<32,256>>>(bs, bi, idx, out + 64*512*256);
    vq_gather_k<<<64,256>>>(cb, idx, z, zq, zqr);
    loss_partial_k<<<256,256>>>(z, zqr, part);
    loss_final_k<<<1,256>>>(part, out + 64*512*256 + 64*128);
    // decoder
    wtr_k<<<(512*512*3+255)/256,256>>>(dw1, wt, 512, 512, 3, 0);
    conv1d_k<512,512,3,1,true,false><<<dim3(1,4,64),256,SM1>>>(zq, wt, db1, g1, 128, 128);
    wtr_k<<<(512*512*4+255)/256,256>>>(dwt2, wt, 512, 512, 4, 1);
    convT1d_k<512,512><<<dim3(2,4,64),256,SMT>>>(g1, wt, dbt2, g2, 128, 256);
    wtr_k<<<(512*256*3+255)/256,256>>>(dw3, wt, 512, 256, 3, 0);
    conv1d_k<512,256,3,1,true,false><<<dim3(2,2,64),256,SM1>>>(g2, wt, db3, g3, 256, 256);
    wtr_k<<<(256*256*4+255)/256,256>>>(dwt4, wt, 256, 256, 4, 1);
    convT1d_k<256,256><<<dim3(4,2,64),256,SMT>>>(g3, wt, dbt4, g4, 256, 512);
    wtr_k<<<(256*256*3+255)/256,256>>>(dw5, wt, 256, 256, 3, 0);
    conv1d_k<256,256,3,1,false,true><<<dim3(4,2,64),256,SM1>>>(g4, wt, db5, out, 512, 512);
}